// round 5
// baseline (speedup 1.0000x reference)
#include <cuda_runtime.h>
#include <cuda_bf16.h>
#include <math.h>
#include <stdint.h>

#define BB   8
#define CIN  64
#define COUT 64
#define CG   16
#define HH   128
#define WW   128

// weight fragments: [p][v(hi/lo)][nt(8)][kt(4)][lane(32)][r(2)] packed bf16x2
__device__ uint32_t g_wfrag[9 * 2 * 2048];

// smem layout (bytes)
#define SOFF_BIAS 0
#define SOFF_KERN 256                 // 9*128*4 = 4608
#define SOFF_B    4864                // 2 x 16384 double buffer (tap0: guide stage)
#define SOFF_XH   37632               // [dh(3)][col(130)][c] stride 72 elems bf16
#define SOFF_XL   93792
#define SMEM_TOTAL 149952

__device__ __forceinline__ uint32_t smem_u32(const void* p) {
    uint32_t a;
    asm("{ .reg .u64 t; cvta.to.shared.u64 t, %1; cvt.u32.u64 %0, t; }"
        : "=r"(a) : "l"(p));
    return a;
}
__device__ __forceinline__ void ldm_x4(uint32_t r[4], uint32_t addr) {
    asm volatile("ldmatrix.sync.aligned.m8n8.x4.shared.b16 {%0,%1,%2,%3}, [%4];"
                 : "=r"(r[0]), "=r"(r[1]), "=r"(r[2]), "=r"(r[3]) : "r"(addr));
}
#define MMA_BF16(d, a, b0, b1)                                                 \
    asm volatile("mma.sync.aligned.m16n8k16.row.col.f32.bf16.bf16.f32 "        \
                 "{%0,%1,%2,%3}, {%4,%5,%6,%7}, {%8,%9}, {%0,%1,%2,%3};"       \
                 : "+f"((d)[0]), "+f"((d)[1]), "+f"((d)[2]), "+f"((d)[3])      \
                 : "r"((a)[0]), "r"((a)[1]), "r"((a)[2]), "r"((a)[3]),         \
                   "r"(b0), "r"(b1))
#define CP_ASYNC16(dst, src)                                                   \
    asm volatile("cp.async.ca.shared.global [%0], [%1], 16;"                   \
                 :: "r"(dst), "l"(src) : "memory")
#define CP_COMMIT() asm volatile("cp.async.commit_group;" ::: "memory")
#define CP_WAIT0()  asm volatile("cp.async.wait_group 0;" ::: "memory")

// ---------------------------------------------------------------------------
// weight prep: shuffle into mma B-fragment order, bf16 hi/lo split.
// ---------------------------------------------------------------------------
__global__ void weight_split(const float* __restrict__ weight) {
    int i = blockIdx.x * 256 + threadIdx.x;
    if (i >= 9 * 2 * 2048) return;
    int p    = i >> 12;
    int v    = (i >> 11) & 1;
    int nt   = (i >> 8) & 7;
    int kt   = (i >> 6) & 3;
    int lane = (i >> 1) & 31;
    int r    = i & 1;
    int o = nt * 8 + (lane >> 2);
    int c = kt * 16 + (lane & 3) * 2 + r * 8;
    float v0 = weight[((size_t)o * CIN + c) * 9 + p];
    float v1 = weight[((size_t)o * CIN + c + 1) * 9 + p];
    __nv_bfloat16 h0 = __float2bfloat16_rn(v0);
    __nv_bfloat16 h1 = __float2bfloat16_rn(v1);
    unsigned short u0, u1;
    if (v == 0) {
        u0 = __bfloat16_as_ushort(h0);
        u1 = __bfloat16_as_ushort(h1);
    } else {
        u0 = __bfloat16_as_ushort(__float2bfloat16_rn(v0 - __bfloat162float(h0)));
        u1 = __bfloat16_as_ushort(__float2bfloat16_rn(v1 - __bfloat162float(h1)));
    }
    g_wfrag[i] = ((uint32_t)u1 << 16) | u0;
}

// ---------------------------------------------------------------------------
// Main: one CTA = one output row (128 pixels) of one image.
// Fused: gaussian kernel compute + PAC conv via mma.sync bf16x3.
// 512 threads = 16 warps: warpM = wid&7 (16 pix), warpN = wid>>3 (32 couts).
// ---------------------------------------------------------------------------
__global__ __launch_bounds__(512, 1)
void pac_mma(const float* __restrict__ x,
             const float* __restrict__ guide,
             const float* __restrict__ bias,
             float* __restrict__ out) {
    extern __shared__ __align__(16) char smem[];
    const uint32_t sb = smem_u32(smem);
    float* bias_s = (float*)(smem + SOFF_BIAS);
    float* kern_s = (float*)(smem + SOFF_KERN);
    float* gs     = (float*)(smem + SOFF_B);     // transient guide stage [c][row][col]
    __nv_bfloat16* xh_s = (__nv_bfloat16*)(smem + SOFF_XH);
    __nv_bfloat16* xl_s = (__nv_bfloat16*)(smem + SOFF_XL);

    const int tid   = threadIdx.x;
    const int lane  = tid & 31;
    const int wid   = tid >> 5;
    const int warpM = wid & 7;
    const int warpN = wid >> 3;
    const int h = blockIdx.x;
    const int b = blockIdx.y;

    // ---- stage guide halo (zero-padded): [c(16)][row(3)][col(130)] ----
    for (int i = tid; i < CG * 3 * 130; i += 512) {
        int col = i % 130;
        int row = (i / 130) % 3;
        int c   = i / 390;
        int gr = h - 1 + row, gc = col - 1;
        float v = 0.f;
        if (gr >= 0 && gr < HH && gc >= 0 && gc < WW)
            v = guide[(((size_t)b * CG + c) * HH + gr) * WW + gc];
        gs[c * 390 + row * 130 + col] = v;
    }
    // ---- stage x halo as bf16 hi/lo, pixel-major: [dh][col][c], stride 72 ----
    for (int i = tid; i < 3 * 130 * CIN; i += 512) {
        int col = i % 130;
        int c   = (i / 130) & 63;
        int dh  = i / (130 * 64);
        int gr = h - 1 + dh, gc = col - 1;
        float v = 0.f;
        if (gr >= 0 && gr < HH && gc >= 0 && gc < WW)
            v = x[(((size_t)b * CIN + c) * HH + gr) * WW + gc];
        __nv_bfloat16 hi = __float2bfloat16_rn(v);
        int off = (dh * 130 + col) * 72 + c;
        xh_s[off] = hi;
        xl_s[off] = __float2bfloat16_rn(v - __bfloat162float(hi));
    }
    if (tid < COUT) bias_s[tid] = bias[tid];
    __syncthreads();

    // ---- compute gaussian taps: threads 0..127, one pixel each ----
    if (tid < 128) {
        const int pix = tid;
        float gc[CG];
#pragma unroll
        for (int c = 0; c < CG; c++) gc[c] = gs[c * 390 + 130 + pix + 1];
#pragma unroll
        for (int p = 0; p < 9; p++) {
            int row = p / 3, colo = pix + p % 3;
            float ss = 0.f;
#pragma unroll
            for (int c = 0; c < CG; c++) {
                float d = gs[c * 390 + row * 130 + colo] - gc[c];
                ss = fmaf(d, d, ss);
            }
            kern_s[p * 128 + pix] = expf(-0.5f * ss);
        }
    }
    __syncthreads();   // kern_s ready; gs region dead -> reusable as B buffer

    // ---- prefetch B for tap 0 ----
    {
        const char* src = (const char*)g_wfrag;
#pragma unroll
        for (int j = 0; j < 2; j++)
            CP_ASYNC16(sb + SOFF_B + (uint32_t)((j * 512 + tid) * 16),
                       src + (j * 512 + tid) * 16);
        CP_COMMIT();
    }

    float acc[4][4];
#pragma unroll
    for (int i = 0; i < 4; i++)
#pragma unroll
        for (int j = 0; j < 4; j++) acc[i][j] = 0.f;

    const uint32_t a_thread =
        (uint32_t)(((lane & 15) * 72 + ((lane >> 4) << 3)) * 2) + warpM * 2304u;

#pragma unroll 1
    for (int p = 0; p < 9; p++) {
        const int dh = p / 3, dw = p - dh * 3;
        const int buf = p & 1;

        CP_WAIT0();        // my cp.async for tap p landed
        __syncthreads();   // all threads' tap-p B visible; p-1 reads done

        if (p + 1 < 9) {   // overlap next-tap B fetch with compute
            const char* src = (const char*)g_wfrag + (p + 1) * 16384;
            uint32_t dstb = sb + SOFF_B + (uint32_t)(((p + 1) & 1) * 16384);
#pragma unroll
            for (int j = 0; j < 2; j++)
                CP_ASYNC16(dstb + (uint32_t)((j * 512 + tid) * 16),
                           src + (j * 512 + tid) * 16);
            CP_COMMIT();
        }

        float T[4][4];
#pragma unroll
        for (int i = 0; i < 4; i++)
#pragma unroll
            for (int j = 0; j < 4; j++) T[i][j] = 0.f;

        const uint32_t a_tap = a_thread + (uint32_t)((dh * 130 + dw) * 144);
        const char* bbase = smem + SOFF_B + buf * 16384;

#pragma unroll
        for (int kt = 0; kt < 4; kt++) {
            uint32_t Ah[4], Al[4];
            uint32_t ad = sb + SOFF_XH + a_tap + (uint32_t)(kt * 32);
            ldm_x4(Ah, ad);
            ldm_x4(Al, ad + (SOFF_XL - SOFF_XH));
#pragma unroll
            for (int nt = 0; nt < 4; nt++) {
                const int ntg = warpN * 4 + nt;
                const uint2* bp = (const uint2*)(bbase +
                    (size_t)(ntg * 1024 + kt * 256) + lane * 8);
                uint2 bh = bp[0];
                uint2 bl = bp[1024];   // lo block = +8192 bytes
                MMA_BF16(T[nt], Ah, bh.x, bh.y);
                MMA_BF16(T[nt], Al, bh.x, bh.y);
                MMA_BF16(T[nt], Ah, bl.x, bl.y);
            }
        }

        // scale by per-pixel gaussian, accumulate
        const int pix0 = warpM * 16 + (lane >> 2);
        const float kv0 = kern_s[p * 128 + pix0];
        const float kv1 = kern_s[p * 128 + pix0 + 8];
#pragma unroll
        for (int nt = 0; nt < 4; nt++) {
            acc[nt][0] = fmaf(kv0, T[nt][0], acc[nt][0]);
            acc[nt][1] = fmaf(kv0, T[nt][1], acc[nt][1]);
            acc[nt][2] = fmaf(kv1, T[nt][2], acc[nt][2]);
            acc[nt][3] = fmaf(kv1, T[nt][3], acc[nt][3]);
        }
    }

    // ---- epilogue: bias + relu ----
    const int pix = warpM * 16 + (lane >> 2);
#pragma unroll
    for (int nt = 0; nt < 4; nt++) {
        int o = (warpN * 4 + nt) * 8 + (lane & 3) * 2;
        float b0 = bias_s[o], b1 = bias_s[o + 1];
        float* op = out + (((size_t)b * COUT + o) * HH + h) * WW;
        op[pix]               = fmaxf(acc[nt][0] + b0, 0.f);
        op[HH * WW + pix]     = fmaxf(acc[nt][1] + b1, 0.f);
        op[pix + 8]           = fmaxf(acc[nt][2] + b0, 0.f);
        op[HH * WW + pix + 8] = fmaxf(acc[nt][3] + b1, 0.f);
    }
}

// ---------------------------------------------------------------------------
extern "C" void kernel_launch(void* const* d_in, const int* in_sizes, int n_in,
                              void* d_out, int out_size) {
    const float* x      = (const float*)d_in[0];   // (8,64,128,128)
    const float* guide  = (const float*)d_in[1];   // (8,16,128,128)
    const float* weight = (const float*)d_in[2];   // (64,64,3,3)
    const float* bias   = (const float*)d_in[3];   // (64,)
    float* out = (float*)d_out;                    // (8,64,128,128)

    (void)in_sizes; (void)n_in; (void)out_size;

    cudaFuncSetAttribute(pac_mma, cudaFuncAttributeMaxDynamicSharedMemorySize,
                         SMEM_TOTAL);

    weight_split<<<(9 * 2 * 2048 + 255) / 256, 256>>>(weight);

    dim3 grid(HH, BB);
    pac_mma<<<grid, 512, SMEM_TOTAL>>>(x, guide, bias, out);
}

// round 7
// speedup vs baseline: 1.1896x; 1.1896x over previous
#include <cuda_runtime.h>
#include <cuda_fp16.h>
#include <math.h>
#include <stdint.h>

#define BB   8
#define CIN  64
#define COUT 64
#define CG   16
#define HH   128
#define WW   128

// weight fragments fp16x2: [p(9)][kt(4)][ng(4)][lane(32)][j(4)]
// j = nt_local*2 + r ; o = (ng*2+nt_local)*8 + lane/4 ; c = kt*16 + (lane%4)*2 + r*8
__device__ uint32_t g_wfrag[9 * 4 * 4 * 32 * 4];

// smem layout (bytes)
#define SOFF_BIAS 0
#define SOFF_KERN 256                  // 9*128*4 = 4608
#define SOFF_B    4864                 // all 9 taps: 9*8192 = 73728
#define SOFF_GS   78592                // guide stage 16*3*130*4 = 24960
#define SOFF_XH   103552               // [dh(3)][col(130)][c(64+pad8)] fp16, 56160
#define SOFF_XL   159712               // 56160
#define SMEM_TOTAL 215872

__device__ __forceinline__ uint32_t smem_u32(const void* p) {
    uint32_t a;
    asm("{ .reg .u64 t; cvta.to.shared.u64 t, %1; cvt.u32.u64 %0, t; }"
        : "=r"(a) : "l"(p));
    return a;
}
__device__ __forceinline__ void ldm_x4(uint32_t r[4], uint32_t addr) {
    asm volatile("ldmatrix.sync.aligned.m8n8.x4.shared.b16 {%0,%1,%2,%3}, [%4];"
                 : "=r"(r[0]), "=r"(r[1]), "=r"(r[2]), "=r"(r[3]) : "r"(addr));
}
#define MMA_F16(d, a, b0, b1)                                                  \
    asm volatile("mma.sync.aligned.m16n8k16.row.col.f32.f16.f16.f32 "          \
                 "{%0,%1,%2,%3}, {%4,%5,%6,%7}, {%8,%9}, {%0,%1,%2,%3};"       \
                 : "+f"((d)[0]), "+f"((d)[1]), "+f"((d)[2]), "+f"((d)[3])      \
                 : "r"((a)[0]), "r"((a)[1]), "r"((a)[2]), "r"((a)[3]),         \
                   "r"(b0), "r"(b1))
#define CP_ASYNC16(dst, src)                                                   \
    asm volatile("cp.async.ca.shared.global [%0], [%1], 16;"                   \
                 :: "r"(dst), "l"(src) : "memory")
#define CP_COMMIT() asm volatile("cp.async.commit_group;" ::: "memory")
#define CP_WAIT0()  asm volatile("cp.async.wait_group 0;" ::: "memory")

// ---------------------------------------------------------------------------
// weight prep: mma B-fragment order, single fp16, LDS.128-pairable layout.
// ---------------------------------------------------------------------------
__global__ void weight_split(const float* __restrict__ weight) {
    int i = blockIdx.x * 256 + threadIdx.x;
    if (i >= 9 * 4 * 4 * 32 * 4) return;
    int p    = i >> 11;
    int kt   = (i >> 9) & 3;
    int ng   = (i >> 7) & 3;
    int lane = (i >> 2) & 31;
    int j    = i & 3;
    int o = (ng * 2 + (j >> 1)) * 8 + (lane >> 2);
    int c = kt * 16 + (lane & 3) * 2 + (j & 1) * 8;
    __half h0 = __float2half_rn(weight[((size_t)o * CIN + c) * 9 + p]);
    __half h1 = __float2half_rn(weight[((size_t)o * CIN + c + 1) * 9 + p]);
    g_wfrag[i] = ((uint32_t)__half_as_ushort(h1) << 16) | __half_as_ushort(h0);
}

// ---------------------------------------------------------------------------
// Main: one CTA = one output row (128 pixels). Fused gaussian + PAC conv.
// mma.sync m16n8k16 fp16 (x hi/lo 2-chain), all-taps B resident, no mainloop
// barriers. 16 warps: warpM = wid&3 (32 pix, mt=2), warpN = wid>>2 (16 couts).
// ---------------------------------------------------------------------------
__global__ __launch_bounds__(512, 1)
void pac_mma(const float* __restrict__ x,
             const float* __restrict__ guide,
             const float* __restrict__ bias,
             float* __restrict__ out) {
    extern __shared__ __align__(16) char smem[];
    const uint32_t sb = smem_u32(smem);
    float* bias_s = (float*)(smem + SOFF_BIAS);
    float* kern_s = (float*)(smem + SOFF_KERN);
    float* gs     = (float*)(smem + SOFF_GS);
    __half* xh_s  = (__half*)(smem + SOFF_XH);
    __half* xl_s  = (__half*)(smem + SOFF_XL);

    const int tid   = threadIdx.x;
    const int lane  = tid & 31;
    const int wid   = tid >> 5;
    const int warpM = wid & 3;
    const int warpN = wid >> 2;
    const int h = blockIdx.x;
    const int b = blockIdx.y;

    // ---- kick off B preload (all 9 taps, 73728B) ----
#pragma unroll
    for (int j = 0; j < 9; j++)
        CP_ASYNC16(sb + SOFF_B + (uint32_t)((j * 512 + tid) * 16),
                   (const char*)g_wfrag + (j * 512 + tid) * 16);
    CP_COMMIT();

    // ---- stage guide halo: [c(16)][row(3)][col(130)] ----
    for (int i = tid; i < CG * 3 * 130; i += 512) {
        int col = i % 130;
        int row = (i / 130) % 3;
        int c   = i / 390;
        int gr = h - 1 + row, gc = col - 1;
        float v = 0.f;
        if (gr >= 0 && gr < HH && gc >= 0 && gc < WW)
            v = guide[(((size_t)b * CG + c) * HH + gr) * WW + gc];
        gs[c * 390 + row * 130 + col] = v;
    }
    // ---- stage x halo as fp16 hi/lo, pixel-major: [dh][col][c], stride 72 ----
    for (int i = tid; i < 3 * 130 * CIN; i += 512) {
        int col = i % 130;
        int c   = (i / 130) & 63;
        int dh  = i / (130 * 64);
        int gr = h - 1 + dh, gc = col - 1;
        float v = 0.f;
        if (gr >= 0 && gr < HH && gc >= 0 && gc < WW)
            v = x[(((size_t)b * CIN + c) * HH + gr) * WW + gc];
        __half hi = __float2half_rn(v);
        int off = (dh * 130 + col) * 72 + c;
        xh_s[off] = hi;
        xl_s[off] = __float2half_rn(v - __half2float(hi));
    }
    if (tid < COUT) bias_s[tid] = bias[tid];
    __syncthreads();

    // ---- gaussian taps: threads 0..127, one pixel each ----
    if (tid < 128) {
        const int pix = tid;
        float gc[CG];
#pragma unroll
        for (int c = 0; c < CG; c++) gc[c] = gs[c * 390 + 130 + pix + 1];
#pragma unroll
        for (int p = 0; p < 9; p++) {
            int row = p / 3, colo = pix + p % 3;
            float ss = 0.f;
#pragma unroll
            for (int c = 0; c < CG; c++) {
                float d = gs[c * 390 + row * 130 + colo] - gc[c];
                ss = fmaf(d, d, ss);
            }
            kern_s[p * 128 + pix] = expf(-0.5f * ss);
        }
    }
    CP_WAIT0();        // own B chunks landed
    __syncthreads();   // kern_s + everyone's B visible

    float acc[2][2][4];
#pragma unroll
    for (int i = 0; i < 2; i++)
#pragma unroll
        for (int j = 0; j < 2; j++)
#pragma unroll
            for (int k = 0; k < 4; k++) acc[i][j][k] = 0.f;

    const uint32_t a_thread =
        (uint32_t)(((lane & 15) * 72 + ((lane >> 4) << 3)) * 2) + warpM * 4608u;
    const uint32_t b_warp = sb + SOFF_B + (uint32_t)(warpN * 512 + lane * 16);

    // ---- mainloop: 9 taps, barrier-free ----
#pragma unroll 1
    for (int p = 0; p < 9; p++) {
        const int dh = p / 3, dw = p - dh * 3;

        float T[2][2][4];
#pragma unroll
        for (int i = 0; i < 2; i++)
#pragma unroll
            for (int j = 0; j < 2; j++)
#pragma unroll
                for (int k = 0; k < 4; k++) T[i][j][k] = 0.f;

        const uint32_t a_tap =
            sb + SOFF_XH + a_thread + (uint32_t)((dh * 130 + dw) * 144);
        const uint32_t b_tap = b_warp + (uint32_t)(p * 8192);

#pragma unroll
        for (int kt = 0; kt < 4; kt++) {
            uint32_t Ah[2][4], Al[2][4];
#pragma unroll
            for (int mt = 0; mt < 2; mt++) {
                uint32_t ad = a_tap + (uint32_t)(kt * 32 + mt * 2304);
                ldm_x4(Ah[mt], ad);
                ldm_x4(Al[mt], ad + (SOFF_XL - SOFF_XH));
            }
            // LDS.128: both nt fragments for this (p, kt)
            uint32_t bx, by, bz, bw;
            asm volatile("ld.shared.v4.u32 {%0,%1,%2,%3}, [%4];"
                         : "=r"(bx), "=r"(by), "=r"(bz), "=r"(bw)
                         : "r"(b_tap + (uint32_t)(kt * 2048)));
#pragma unroll
            for (int mt = 0; mt < 2; mt++) {
                MMA_F16(T[mt][0], Ah[mt], bx, by);
                MMA_F16(T[mt][0], Al[mt], bx, by);
                MMA_F16(T[mt][1], Ah[mt], bz, bw);
                MMA_F16(T[mt][1], Al[mt], bz, bw);
            }
        }

        // fold per-pixel gaussian into accumulators
#pragma unroll
        for (int mt = 0; mt < 2; mt++) {
            const int pix0 = warpM * 32 + mt * 16 + (lane >> 2);
            const float kv0 = kern_s[p * 128 + pix0];
            const float kv1 = kern_s[p * 128 + pix0 + 8];
#pragma unroll
            for (int nt = 0; nt < 2; nt++) {
                acc[mt][nt][0] = fmaf(kv0, T[mt][nt][0], acc[mt][nt][0]);
                acc[mt][nt][1] = fmaf(kv0, T[mt][nt][1], acc[mt][nt][1]);
                acc[mt][nt][2] = fmaf(kv1, T[mt][nt][2], acc[mt][nt][2]);
                acc[mt][nt][3] = fmaf(kv1, T[mt][nt][3], acc[mt][nt][3]);
            }
        }
    }

    // ---- epilogue: bias + relu ----
#pragma unroll
    for (int mt = 0; mt < 2; mt++) {
        const int pix = warpM * 32 + mt * 16 + (lane >> 2);
#pragma unroll
        for (int nt = 0; nt < 2; nt++) {
            int o = (warpN * 2 + nt) * 8 + (lane & 3) * 2;
            float b0 = bias_s[o], b1 = bias_s[o + 1];
            float* op = out + (((size_t)b * COUT + o) * HH + h) * WW;
            op[pix]               = fmaxf(acc[mt][nt][0] + b0, 0.f);
            op[HH * WW + pix]     = fmaxf(acc[mt][nt][1] + b1, 0.f);
            op[pix + 8]           = fmaxf(acc[mt][nt][2] + b0, 0.f);
            op[HH * WW + pix + 8] = fmaxf(acc[mt][nt][3] + b1, 0.f);
        }
    }
}

// ---------------------------------------------------------------------------
extern "C" void kernel_launch(void* const* d_in, const int* in_sizes, int n_in,
                              void* d_out, int out_size) {
    const float* x      = (const float*)d_in[0];   // (8,64,128,128)
    const float* guide  = (const float*)d_in[1];   // (8,16,128,128)
    const float* weight = (const float*)d_in[2];   // (64,64,3,3)
    const float* bias   = (const float*)d_in[3];   // (64,)
    float* out = (float*)d_out;                    // (8,64,128,128)

    (void)in_sizes; (void)n_in; (void)out_size;

    cudaFuncSetAttribute(pac_mma, cudaFuncAttributeMaxDynamicSharedMemorySize,
                         SMEM_TOTAL);

    weight_split<<<(9 * 4 * 4 * 32 * 4 + 255) / 256, 256>>>(weight);

    dim3 grid(HH, BB);
    pac_mma<<<grid, 512, SMEM_TOTAL>>>(x, guide, bias, out);
}

// round 8
// speedup vs baseline: 1.4061x; 1.1821x over previous
#include <cuda_runtime.h>
#include <cuda_fp16.h>
#include <math.h>
#include <stdint.h>

#define BB   8
#define CIN  64
#define COUT 64
#define CG   16
#define HH   128
#define WW   128

// weight fragments fp16x2: [p(9)][kt(4)][ng(4)][lane(32)][j(4)]
// j = nt_local*2 + r ; o = (ng*2+nt_local)*8 + lane/4 ; c = kt*16 + (lane%4)*2 + r*8
__device__ uint32_t g_wfrag[9 * 4 * 4 * 32 * 4];

// smem layout (bytes)
#define SOFF_BIAS 0
#define SOFF_KERN 256                  // 9*128*4 = 4608
#define SOFF_B    4864                 // all 9 taps: 9*8192 = 73728
#define SOFF_GS   78592                // guide stage 16*3*130*4 = 24960
#define SOFF_XH   103552               // [dh(3)][col(130)][c(64+pad8)] fp16, 56160
#define SMEM_TOTAL 159712

__device__ __forceinline__ uint32_t smem_u32(const void* p) {
    uint32_t a;
    asm("{ .reg .u64 t; cvta.to.shared.u64 t, %1; cvt.u32.u64 %0, t; }"
        : "=r"(a) : "l"(p));
    return a;
}
__device__ __forceinline__ void ldm_x4(uint32_t r[4], uint32_t addr) {
    asm volatile("ldmatrix.sync.aligned.m8n8.x4.shared.b16 {%0,%1,%2,%3}, [%4];"
                 : "=r"(r[0]), "=r"(r[1]), "=r"(r[2]), "=r"(r[3]) : "r"(addr));
}
#define MMA_F16(d, a, b0, b1)                                                  \
    asm volatile("mma.sync.aligned.m16n8k16.row.col.f32.f16.f16.f32 "          \
                 "{%0,%1,%2,%3}, {%4,%5,%6,%7}, {%8,%9}, {%0,%1,%2,%3};"       \
                 : "+f"((d)[0]), "+f"((d)[1]), "+f"((d)[2]), "+f"((d)[3])      \
                 : "r"((a)[0]), "r"((a)[1]), "r"((a)[2]), "r"((a)[3]),         \
                   "r"(b0), "r"(b1))
#define CP_ASYNC16(dst, src)                                                   \
    asm volatile("cp.async.ca.shared.global [%0], [%1], 16;"                   \
                 :: "r"(dst), "l"(src) : "memory")
#define CP_COMMIT() asm volatile("cp.async.commit_group;" ::: "memory")
#define CP_WAIT0()  asm volatile("cp.async.wait_group 0;" ::: "memory")

// ---------------------------------------------------------------------------
// weight prep: mma B-fragment order, single fp16, LDS.128-pairable layout.
// ---------------------------------------------------------------------------
__global__ void weight_split(const float* __restrict__ weight) {
    int i = blockIdx.x * 256 + threadIdx.x;
    if (i >= 9 * 4 * 4 * 32 * 4) return;
    int p    = i >> 11;
    int kt   = (i >> 9) & 3;
    int ng   = (i >> 7) & 3;
    int lane = (i >> 2) & 31;
    int j    = i & 3;
    int o = (ng * 2 + (j >> 1)) * 8 + (lane >> 2);
    int c = kt * 16 + (lane & 3) * 2 + (j & 1) * 8;
    __half h0 = __float2half_rn(weight[((size_t)o * CIN + c) * 9 + p]);
    __half h1 = __float2half_rn(weight[((size_t)o * CIN + c + 1) * 9 + p]);
    g_wfrag[i] = ((uint32_t)__half_as_ushort(h1) << 16) | __half_as_ushort(h0);
}

// ---------------------------------------------------------------------------
// Main: one CTA = one output row (128 pixels). Fused gaussian + PAC conv.
// mma.sync m16n8k16 fp16 (single chain), all-taps B resident, no mainloop
// barriers, fully unrolled taps.
// 16 warps: warpM = wid&3 (32 pix, mt=2), warpN = wid>>2 (16 couts).
// ---------------------------------------------------------------------------
__global__ __launch_bounds__(512, 1)
void pac_mma(const float* __restrict__ x,
             const float* __restrict__ guide,
             const float* __restrict__ bias,
             float* __restrict__ out) {
    extern __shared__ __align__(16) char smem[];
    const uint32_t sb = smem_u32(smem);
    float* bias_s = (float*)(smem + SOFF_BIAS);
    float* kern_s = (float*)(smem + SOFF_KERN);
    float* gs     = (float*)(smem + SOFF_GS);
    __half* xh_s  = (__half*)(smem + SOFF_XH);

    const int tid   = threadIdx.x;
    const int lane  = tid & 31;
    const int wid   = tid >> 5;
    const int warpM = wid & 3;
    const int warpN = wid >> 2;
    const int h = blockIdx.x;
    const int b = blockIdx.y;

    // ---- kick off B preload (all 9 taps, 73728B) ----
#pragma unroll
    for (int j = 0; j < 9; j++)
        CP_ASYNC16(sb + SOFF_B + (uint32_t)((j * 512 + tid) * 16),
                   (const char*)g_wfrag + (j * 512 + tid) * 16);
    CP_COMMIT();

    // ---- stage guide halo: [c(16)][row(3)][col(130)] ----
    for (int i = tid; i < CG * 3 * 130; i += 512) {
        int col = i % 130;
        int row = (i / 130) % 3;
        int c   = i / 390;
        int gr = h - 1 + row, gc = col - 1;
        float v = 0.f;
        if (gr >= 0 && gr < HH && gc >= 0 && gc < WW)
            v = guide[(((size_t)b * CG + c) * HH + gr) * WW + gc];
        gs[c * 390 + row * 130 + col] = v;
    }
    // ---- stage x halo as fp16, pixel-major: [dh][col][c], stride 72 ----
    for (int i = tid; i < 3 * 130 * CIN; i += 512) {
        int col = i % 130;
        int c   = (i / 130) & 63;
        int dh  = i / (130 * 64);
        int gr = h - 1 + dh, gc = col - 1;
        float v = 0.f;
        if (gr >= 0 && gr < HH && gc >= 0 && gc < WW)
            v = x[(((size_t)b * CIN + c) * HH + gr) * WW + gc];
        xh_s[(dh * 130 + col) * 72 + c] = __float2half_rn(v);
    }
    if (tid < COUT) bias_s[tid] = bias[tid];
    __syncthreads();

    // ---- gaussian taps: threads 0..127, one pixel each ----
    if (tid < 128) {
        const int pix = tid;
        float gc[CG];
#pragma unroll
        for (int c = 0; c < CG; c++) gc[c] = gs[c * 390 + 130 + pix + 1];
#pragma unroll
        for (int p = 0; p < 9; p++) {
            int row = p / 3, colo = pix + p % 3;
            float ss = 0.f;
#pragma unroll
            for (int c = 0; c < CG; c++) {
                float d = gs[c * 390 + row * 130 + colo] - gc[c];
                ss = fmaf(d, d, ss);
            }
            kern_s[p * 128 + pix] = expf(-0.5f * ss);
        }
    }
    CP_WAIT0();        // own B chunks landed
    __syncthreads();   // kern_s + everyone's B visible

    float acc[2][2][4];
#pragma unroll
    for (int i = 0; i < 2; i++)
#pragma unroll
        for (int j = 0; j < 2; j++)
#pragma unroll
            for (int k = 0; k < 4; k++) acc[i][j][k] = 0.f;

    const uint32_t a_base = sb + SOFF_XH +
        (uint32_t)(((lane & 15) * 72 + ((lane >> 4) << 3)) * 2) + warpM * 4608u;
    const uint32_t b_base = sb + SOFF_B + (uint32_t)(warpN * 512 + lane * 16);
    const int pix0 = warpM * 32 + (lane >> 2);

    // ---- mainloop: 9 taps, fully unrolled, barrier-free ----
#pragma unroll
    for (int p = 0; p < 9; p++) {
        const int dh = p / 3, dw = p - dh * 3;

        float T[2][2][4];
#pragma unroll
        for (int i = 0; i < 2; i++)
#pragma unroll
            for (int j = 0; j < 2; j++)
#pragma unroll
                for (int k = 0; k < 4; k++) T[i][j][k] = 0.f;

        const uint32_t a_tap = a_base + (uint32_t)((dh * 130 + dw) * 144);
        const uint32_t b_tap = b_base + (uint32_t)(p * 8192);

#pragma unroll
        for (int kt = 0; kt < 4; kt++) {
            uint32_t Ah[2][4];
            ldm_x4(Ah[0], a_tap + (uint32_t)(kt * 32));
            ldm_x4(Ah[1], a_tap + (uint32_t)(kt * 32 + 2304));
            uint32_t bx, by, bz, bw;
            asm volatile("ld.shared.v4.u32 {%0,%1,%2,%3}, [%4];"
                         : "=r"(bx), "=r"(by), "=r"(bz), "=r"(bw)
                         : "r"(b_tap + (uint32_t)(kt * 2048)));
#pragma unroll
            for (int mt = 0; mt < 2; mt++) {
                MMA_F16(T[mt][0], Ah[mt], bx, by);
                MMA_F16(T[mt][1], Ah[mt], bz, bw);
            }
        }

        // fold per-pixel gaussian into accumulators
#pragma unroll
        for (int mt = 0; mt < 2; mt++) {
            const float kv0 = kern_s[p * 128 + pix0 + mt * 16];
            const float kv1 = kern_s[p * 128 + pix0 + mt * 16 + 8];
#pragma unroll
            for (int nt = 0; nt < 2; nt++) {
                acc[mt][nt][0] = fmaf(kv0, T[mt][nt][0], acc[mt][nt][0]);
                acc[mt][nt][1] = fmaf(kv0, T[mt][nt][1], acc[mt][nt][1]);
                acc[mt][nt][2] = fmaf(kv1, T[mt][nt][2], acc[mt][nt][2]);
                acc[mt][nt][3] = fmaf(kv1, T[mt][nt][3], acc[mt][nt][3]);
            }
        }
    }

    // ---- epilogue: bias + relu ----
#pragma unroll
    for (int mt = 0; mt < 2; mt++) {
        const int pix = pix0 + mt * 16;
#pragma unroll
        for (int nt = 0; nt < 2; nt++) {
            int o = (warpN * 2 + nt) * 8 + (lane & 3) * 2;
            float b0 = bias_s[o], b1 = bias_s[o + 1];
            float* op = out + (((size_t)b * COUT + o) * HH + h) * WW;
            op[pix]               = fmaxf(acc[mt][nt][0] + b0, 0.f);
            op[HH * WW + pix]     = fmaxf(acc[mt][nt][1] + b1, 0.f);
            op[pix + 8]           = fmaxf(acc[mt][nt][2] + b0, 0.f);
            op[HH * WW + pix + 8] = fmaxf(acc[mt][nt][3] + b1, 0.f);
        }
    }
}

// ---------------------------------------------------------------------------
extern "C" void kernel_launch(void* const* d_in, const int* in_sizes, int n_in,
                              void* d_out, int out_size) {
    const float* x      = (const float*)d_in[0];   // (8,64,128,128)
    const float* guide  = (const float*)d_in[1];   // (8,16,128,128)
    const float* weight = (const float*)d_in[2];   // (64,64,3,3)
    const float* bias   = (const float*)d_in[3];   // (64,)
    float* out = (float*)d_out;                    // (8,64,128,128)

    (void)in_sizes; (void)n_in; (void)out_size;

    cudaFuncSetAttribute(pac_mma, cudaFuncAttributeMaxDynamicSharedMemorySize,
                         SMEM_TOTAL);

    weight_split<<<(9 * 4 * 4 * 32 * 4 + 255) / 256, 256>>>(weight);

    dim3 grid(HH, BB);
    pac_mma<<<grid, 512, SMEM_TOTAL>>>(x, guide, bias, out);
}

// round 10
// speedup vs baseline: 1.7173x; 1.2213x over previous
#include <cuda_runtime.h>
#include <cuda_fp16.h>
#include <math.h>
#include <stdint.h>

#define BB   8
#define CIN  64
#define COUT 64
#define CG   16
#define HH   128
#define WW   128

// weight fragments fp16x2: [p(9)][kt(4)][ng(4)][lane(32)][j(4)]
// j = nt_local*2 + r ; o = (ng*2+nt_local)*8 + lane/4 ; c = kt*16 + (lane%4)*2 + r*8
__device__ uint32_t g_wfrag[9 * 4 * 4 * 32 * 4];

// smem layout (bytes)
#define SOFF_BIAS 0                    // 256
#define SOFF_KERN 256                  // 9*128 half2 (4B) = 4608
#define SOFF_XH   4864                 // [dh(3)][col(130)][c(64, pad to 72)] fp16
#define SMEM_TOTAL (4864 + 3 * 130 * 72 * 2)   // 61024

__device__ __forceinline__ uint32_t smem_u32(const void* p) {
    uint32_t a;
    asm("{ .reg .u64 t; cvta.to.shared.u64 t, %1; cvt.u32.u64 %0, t; }"
        : "=r"(a) : "l"(p));
    return a;
}
__device__ __forceinline__ void ldm_x4(uint32_t r[4], uint32_t addr) {
    asm volatile("ldmatrix.sync.aligned.m8n8.x4.shared.b16 {%0,%1,%2,%3}, [%4];"
                 : "=r"(r[0]), "=r"(r[1]), "=r"(r[2]), "=r"(r[3]) : "r"(addr));
}
__device__ __forceinline__ uint32_t hmul2(uint32_t a, uint32_t k) {
    uint32_t d;
    asm("mul.f16x2 %0, %1, %2;" : "=r"(d) : "r"(a), "r"(k));
    return d;
}
#define MMA_F16(d, a, b0, b1)                                                  \
    asm volatile("mma.sync.aligned.m16n8k16.row.col.f32.f16.f16.f32 "          \
                 "{%0,%1,%2,%3}, {%4,%5,%6,%7}, {%8,%9}, {%0,%1,%2,%3};"       \
                 : "+f"((d)[0]), "+f"((d)[1]), "+f"((d)[2]), "+f"((d)[3])      \
                 : "r"((a)[0]), "r"((a)[1]), "r"((a)[2]), "r"((a)[3]),         \
                   "r"(b0), "r"(b1))

// ---------------------------------------------------------------------------
// weight prep: mma B-fragment order, fp16
// ---------------------------------------------------------------------------
__global__ void weight_split(const float* __restrict__ weight) {
    int i = blockIdx.x * 256 + threadIdx.x;
    if (i >= 9 * 4 * 4 * 32 * 4) return;
    int p    = i >> 11;
    int kt   = (i >> 9) & 3;
    int ng   = (i >> 7) & 3;
    int lane = (i >> 2) & 31;
    int j    = i & 3;
    int o = (ng * 2 + (j >> 1)) * 8 + (lane >> 2);
    int c = kt * 16 + (lane & 3) * 2 + (j & 1) * 8;
    __half h0 = __float2half_rn(weight[((size_t)o * CIN + c) * 9 + p]);
    __half h1 = __float2half_rn(weight[((size_t)o * CIN + c + 1) * 9 + p]);
    g_wfrag[i] = ((uint32_t)__half_as_ushort(h1) << 16) | __half_as_ushort(h0);
}

// ---------------------------------------------------------------------------
// Main: one CTA = one output row (128 pix). kv folded into A fragments (f16x2),
// MMA accumulates straight into acc. B via LDG.128 from L2. 2 CTAs/SM.
// 16 warps: warpM = wid&3 (32 pix, mt=2), warpN = wid>>2 (16 couts).
// A-fragment row map: A[0],A[2] -> pixel g ; A[1],A[3] -> pixel g+8.
// ---------------------------------------------------------------------------
__global__ __launch_bounds__(512, 2)
void pac_mma(const float* __restrict__ x,
             const float* __restrict__ guide,
             const float* __restrict__ bias,
             float* __restrict__ out) {
    extern __shared__ __align__(16) char smem[];
    const uint32_t sb = smem_u32(smem);
    float*    bias_s = (float*)(smem + SOFF_BIAS);
    uint32_t* kern_s = (uint32_t*)(smem + SOFF_KERN);   // half2(kv,kv)
    __half*   xh_s   = (__half*)(smem + SOFF_XH);

    const int tid   = threadIdx.x;
    const int lane  = tid & 31;
    const int wid   = tid >> 5;
    const int warpM = wid & 3;
    const int warpN = wid >> 2;
    const int h = blockIdx.x;
    const int b = blockIdx.y;

    // ---- stage x halo fp16, pixel-major [dh][col][c] stride 72, no division ----
#pragma unroll
    for (int dh = 0; dh < 3; dh++) {
        const int gr = h - 1 + dh;
        const bool rok = (gr >= 0) && (gr < HH);
        const float4* xr = (const float4*)x +
                           ((size_t)b * CIN * HH + gr) * (WW / 4);
#pragma unroll
        for (int k = 0; k < 4; k++) {
            int i  = tid + k * 512;        // 0..2047
            int c  = i >> 5;               // 0..63
            int g4 = i & 31;               // float4 idx; gc = g4*4
            float4 v = make_float4(0.f, 0.f, 0.f, 0.f);
            if (rok) v = xr[(size_t)c * (HH * WW / 4) + g4];
            __half* dst = xh_s + (dh * 130 + g4 * 4 + 1) * 72 + c;
            dst[0]       = __float2half_rn(v.x);
            dst[72]      = __float2half_rn(v.y);
            dst[144]     = __float2half_rn(v.z);
            dst[216]     = __float2half_rn(v.w);
        }
    }
    // edge cols (gc = -1 and 128 -> zero pad)
    if (tid < 192) {
        int dh = tid >> 6, c = tid & 63;
        xh_s[(dh * 130 + 0)   * 72 + c] = __ushort_as_half((unsigned short)0);
        xh_s[(dh * 130 + 129) * 72 + c] = __ushort_as_half((unsigned short)0);
    }
    if (tid < COUT) bias_s[tid] = bias[tid];

    // ---- gaussian taps from global guide (coalesced), store half2(kv,kv) ----
    if (tid < 128) {
        const int pix = tid;
        const float* gb = guide + (size_t)b * CG * HH * WW;
        float gc[CG];
#pragma unroll
        for (int c = 0; c < CG; c++)
            gc[c] = __ldg(&gb[c * HH * WW + h * WW + pix]);
#pragma unroll
        for (int p = 0; p < 9; p++) {
            int gr = h - 1 + p / 3;
            int gw = pix - 1 + p % 3;
            float ss = 0.f;
            if (gr >= 0 && gr < HH && gw >= 0 && gw < WW) {
#pragma unroll
                for (int c = 0; c < CG; c++) {
                    float d = __ldg(&gb[c * HH * WW + gr * WW + gw]) - gc[c];
                    ss = fmaf(d, d, ss);
                }
            } else {
#pragma unroll
                for (int c = 0; c < CG; c++) ss = fmaf(gc[c], gc[c], ss);
            }
            float kv = __expf(-0.5f * ss);
            __half kh = __float2half_rn(kv);
            uint32_t u = __half_as_ushort(kh);
            kern_s[p * 128 + pix] = (u << 16) | u;
        }
    }
    __syncthreads();

    float acc[2][2][4];
#pragma unroll
    for (int i = 0; i < 2; i++)
#pragma unroll
        for (int j = 0; j < 2; j++)
#pragma unroll
            for (int k = 0; k < 4; k++) acc[i][j][k] = 0.f;

    const uint32_t a_base = sb + SOFF_XH +
        (uint32_t)(((lane & 15) * 72 + ((lane >> 4) << 3)) * 2) + warpM * 4608u;
    const uint4* b_base = (const uint4*)g_wfrag + (size_t)warpN * 32 + lane;
    const int pix0 = warpM * 32 + (lane >> 2);

    // ---- mainloop: 9 taps, barrier-free, kv folded into A ----
#pragma unroll
    for (int p = 0; p < 9; p++) {
        const int dh = p / 3, dw = p - dh * 3;
        const uint32_t a_tap = a_base + (uint32_t)((dh * 130 + dw) * 144);
        const uint4* b_tap = b_base + (size_t)p * 512;   // p*4*4*32 uint4

        uint32_t kv2[2][2];
#pragma unroll
        for (int mt = 0; mt < 2; mt++) {
            kv2[mt][0] = kern_s[p * 128 + pix0 + mt * 16];      // pixel g
            kv2[mt][1] = kern_s[p * 128 + pix0 + mt * 16 + 8];  // pixel g+8
        }

#pragma unroll
        for (int kt = 0; kt < 4; kt++) {
            uint4 bw = __ldg(b_tap + (size_t)kt * 128);
#pragma unroll
            for (int mt = 0; mt < 2; mt++) {
                uint32_t A[4];
                ldm_x4(A, a_tap + (uint32_t)(kt * 32 + mt * 2304));
                // row map: A[0],A[2] -> pixel g ; A[1],A[3] -> pixel g+8
                A[0] = hmul2(A[0], kv2[mt][0]);
                A[2] = hmul2(A[2], kv2[mt][0]);
                A[1] = hmul2(A[1], kv2[mt][1]);
                A[3] = hmul2(A[3], kv2[mt][1]);
                MMA_F16(acc[mt][0], A, bw.x, bw.y);
                MMA_F16(acc[mt][1], A, bw.z, bw.w);
            }
        }
    }

    // ---- epilogue: bias + relu ----
#pragma unroll
    for (int mt = 0; mt < 2; mt++) {
        const int pix = pix0 + mt * 16;
#pragma unroll
        for (int nt = 0; nt < 2; nt++) {
            int o = (warpN * 2 + nt) * 8 + (lane & 3) * 2;
            float b0 = bias_s[o], b1 = bias_s[o + 1];
            float* op = out + (((size_t)b * COUT + o) * HH + h) * WW;
            op[pix]               = fmaxf(acc[mt][nt][0] + b0, 0.f);
            op[HH * WW + pix]     = fmaxf(acc[mt][nt][1] + b1, 0.f);
            op[pix + 8]           = fmaxf(acc[mt][nt][2] + b0, 0.f);
            op[HH * WW + pix + 8] = fmaxf(acc[mt][nt][3] + b1, 0.f);
        }
    }
}

// ---------------------------------------------------------------------------
extern "C" void kernel_launch(void* const* d_in, const int* in_sizes, int n_in,
                              void* d_out, int out_size) {
    const float* x      = (const float*)d_in[0];   // (8,64,128,128)
    const float* guide  = (const float*)d_in[1];   // (8,16,128,128)
    const float* weight = (const float*)d_in[2];   // (64,64,3,3)
    const float* bias   = (const float*)d_in[3];   // (64,)
    float* out = (float*)d_out;                    // (8,64,128,128)

    (void)in_sizes; (void)n_in; (void)out_size;

    cudaFuncSetAttribute(pac_mma, cudaFuncAttributeMaxDynamicSharedMemorySize,
                         SMEM_TOTAL);

    weight_split<<<(9 * 4 * 4 * 32 * 4 + 255) / 256, 256>>>(weight);

    dim3 grid(HH, BB);
    pac_mma<<<grid, 512, SMEM_TOTAL>>>(x, guide, bias, out);
}

// round 11
// speedup vs baseline: 2.8372x; 1.6521x over previous
#include <cuda_runtime.h>
#include <cuda_fp16.h>
#include <math.h>
#include <stdint.h>

#define BB   8
#define CIN  64
#define COUT 64
#define CG   16
#define HH   128
#define WW   128

// weight fragments fp16x2: [p(9)][kt(4)][ng(4)][lane(32)][j(4)]
// j = nt_local*2 + r ; o = (ng*2+nt_local)*8 + lane/4 ; c = kt*16 + (lane%4)*2 + r*8
__device__ uint32_t g_wfrag[9 * 4 * 4 * 32 * 4];

// smem layout (bytes)
#define SOFF_BIAS 0                    // 256
#define SOFF_KERN 256                  // 9*128 half2 (4B) = 4608
#define SOFF_XH   4864                 // [dh(3)][col(130)][c(64, pad to 72)] fp16
#define SMEM_TOTAL (4864 + 3 * 130 * 72 * 2)   // 61024

__device__ __forceinline__ uint32_t smem_u32(const void* p) {
    uint32_t a;
    asm("{ .reg .u64 t; cvta.to.shared.u64 t, %1; cvt.u32.u64 %0, t; }"
        : "=r"(a) : "l"(p));
    return a;
}
__device__ __forceinline__ void ldm_x4(uint32_t r[4], uint32_t addr) {
    asm volatile("ldmatrix.sync.aligned.m8n8.x4.shared.b16 {%0,%1,%2,%3}, [%4];"
                 : "=r"(r[0]), "=r"(r[1]), "=r"(r[2]), "=r"(r[3]) : "r"(addr));
}
__device__ __forceinline__ uint32_t hmul2(uint32_t a, uint32_t k) {
    uint32_t d;
    asm("mul.f16x2 %0, %1, %2;" : "=r"(d) : "r"(a), "r"(k));
    return d;
}
#define MMA_F16(d, a, b0, b1)                                                  \
    asm volatile("mma.sync.aligned.m16n8k16.row.col.f32.f16.f16.f32 "          \
                 "{%0,%1,%2,%3}, {%4,%5,%6,%7}, {%8,%9}, {%0,%1,%2,%3};"       \
                 : "+f"((d)[0]), "+f"((d)[1]), "+f"((d)[2]), "+f"((d)[3])      \
                 : "r"((a)[0]), "r"((a)[1]), "r"((a)[2]), "r"((a)[3]),         \
                   "r"(b0), "r"(b1))

// ---------------------------------------------------------------------------
// weight prep: mma B-fragment order, fp16
// ---------------------------------------------------------------------------
__global__ void weight_split(const float* __restrict__ weight) {
    int i = blockIdx.x * 256 + threadIdx.x;
    if (i >= 9 * 4 * 4 * 32 * 4) return;
    int p    = i >> 11;
    int kt   = (i >> 9) & 3;
    int ng   = (i >> 7) & 3;
    int lane = (i >> 2) & 31;
    int j    = i & 3;
    int o = (ng * 2 + (j >> 1)) * 8 + (lane >> 2);
    int c = kt * 16 + (lane & 3) * 2 + (j & 1) * 8;
    __half h0 = __float2half_rn(weight[((size_t)o * CIN + c) * 9 + p]);
    __half h1 = __float2half_rn(weight[((size_t)o * CIN + c + 1) * 9 + p]);
    g_wfrag[i] = ((uint32_t)__half_as_ushort(h1) << 16) | __half_as_ushort(h0);
}

// ---------------------------------------------------------------------------
// Main: one CTA = one output row (128 pix). kv folded into A fragments (f16x2),
// MMA accumulates straight into acc. B via LDG.128 from L2. 2 CTAs/SM.
// 16 warps: warpM = wid&3 (32 pix, mt=2), warpN = wid>>2 (16 couts).
// Staging: one STS.128 per (dh,col,c_oct) item -> conflict-free (4-phase floor).
// ---------------------------------------------------------------------------
__global__ __launch_bounds__(512, 2)
void pac_mma(const float* __restrict__ x,
             const float* __restrict__ guide,
             const float* __restrict__ bias,
             float* __restrict__ out) {
    extern __shared__ __align__(16) char smem[];
    const uint32_t sb = smem_u32(smem);
    float*    bias_s = (float*)(smem + SOFF_BIAS);
    uint32_t* kern_s = (uint32_t*)(smem + SOFF_KERN);   // half2(kv,kv)
    __half*   xh_s   = (__half*)(smem + SOFF_XH);

    const int tid   = threadIdx.x;
    const int lane  = tid & 31;
    const int wid   = tid >> 5;
    const int warpM = wid & 3;
    const int warpN = wid >> 2;
    const int h = blockIdx.x;
    const int b = blockIdx.y;

    // ---- stage x halo fp16, [dh][col][c] stride 72; 1 STS.128 per item ----
    // item i -> col = i%130 (lane-consecutive => coalesced LDG + conflict-free STS)
    //           t = i/130 : c_oct = t&7, dh = t>>3   (3*8*130 = 3120 items)
    for (int i = tid; i < 3120; i += 512) {
        int col = i % 130;
        int t   = i / 130;
        int c0  = (t & 7) * 8;
        int dh  = t >> 3;
        int gr = h - 1 + dh, gc = col - 1;
        const bool ok = (gr >= 0) && (gr < HH) && (gc >= 0) && (gc < WW);
        const float* xp = x + ((size_t)(b * CIN + c0) * HH + gr) * WW + gc;
        __half hv[8];
#pragma unroll
        for (int j = 0; j < 8; j++) {
            float v = ok ? __ldg(xp + (size_t)j * (HH * WW)) : 0.f;
            hv[j] = __float2half_rn(v);
        }
        *(uint4*)(xh_s + (dh * 130 + col) * 72 + c0) = *(const uint4*)hv;
    }
    if (tid < COUT) bias_s[tid] = bias[tid];

    // ---- gaussian taps from global guide (coalesced), store half2(kv,kv) ----
    if (tid < 128) {
        const int pix = tid;
        const float* gb = guide + (size_t)b * CG * HH * WW;
        float gc[CG];
#pragma unroll
        for (int c = 0; c < CG; c++)
            gc[c] = __ldg(&gb[c * HH * WW + h * WW + pix]);
#pragma unroll
        for (int p = 0; p < 9; p++) {
            int gr = h - 1 + p / 3;
            int gw = pix - 1 + p % 3;
            float ss = 0.f;
            if (gr >= 0 && gr < HH && gw >= 0 && gw < WW) {
#pragma unroll
                for (int c = 0; c < CG; c++) {
                    float d = __ldg(&gb[c * HH * WW + gr * WW + gw]) - gc[c];
                    ss = fmaf(d, d, ss);
                }
            } else {
#pragma unroll
                for (int c = 0; c < CG; c++) ss = fmaf(gc[c], gc[c], ss);
            }
            float kv = __expf(-0.5f * ss);
            __half kh = __float2half_rn(kv);
            uint32_t u = __half_as_ushort(kh);
            kern_s[p * 128 + pix] = (u << 16) | u;
        }
    }
    __syncthreads();

    float acc[2][2][4];
#pragma unroll
    for (int i = 0; i < 2; i++)
#pragma unroll
        for (int j = 0; j < 2; j++)
#pragma unroll
            for (int k = 0; k < 4; k++) acc[i][j][k] = 0.f;

    const uint32_t a_base = sb + SOFF_XH +
        (uint32_t)(((lane & 15) * 72 + ((lane >> 4) << 3)) * 2) + warpM * 4608u;
    const uint4* b_base = (const uint4*)g_wfrag + (size_t)warpN * 32 + lane;
    const int pix0 = warpM * 32 + (lane >> 2);

    // ---- mainloop: 9 taps, barrier-free, kv folded into A ----
#pragma unroll
    for (int p = 0; p < 9; p++) {
        const int dh = p / 3, dw = p - dh * 3;
        const uint32_t a_tap = a_base + (uint32_t)((dh * 130 + dw) * 144);
        const uint4* b_tap = b_base + (size_t)p * 512;   // p*4*4*32 uint4

        uint32_t kv2[2][2];
#pragma unroll
        for (int mt = 0; mt < 2; mt++) {
            kv2[mt][0] = kern_s[p * 128 + pix0 + mt * 16];      // pixel g
            kv2[mt][1] = kern_s[p * 128 + pix0 + mt * 16 + 8];  // pixel g+8
        }

#pragma unroll
        for (int kt = 0; kt < 4; kt++) {
            uint4 bw = __ldg(b_tap + (size_t)kt * 128);
#pragma unroll
            for (int mt = 0; mt < 2; mt++) {
                uint32_t A[4];
                ldm_x4(A, a_tap + (uint32_t)(kt * 32 + mt * 2304));
                // row map: A[0],A[2] -> pixel g ; A[1],A[3] -> pixel g+8
                A[0] = hmul2(A[0], kv2[mt][0]);
                A[2] = hmul2(A[2], kv2[mt][0]);
                A[1] = hmul2(A[1], kv2[mt][1]);
                A[3] = hmul2(A[3], kv2[mt][1]);
                MMA_F16(acc[mt][0], A, bw.x, bw.y);
                MMA_F16(acc[mt][1], A, bw.z, bw.w);
            }
        }
    }

    // ---- epilogue: bias + relu ----
#pragma unroll
    for (int mt = 0; mt < 2; mt++) {
        const int pix = pix0 + mt * 16;
#pragma unroll
        for (int nt = 0; nt < 2; nt++) {
            int o = (warpN * 2 + nt) * 8 + (lane & 3) * 2;
            float b0 = bias_s[o], b1 = bias_s[o + 1];
            float* op = out + (((size_t)b * COUT + o) * HH + h) * WW;
            op[pix]               = fmaxf(acc[mt][nt][0] + b0, 0.f);
            op[HH * WW + pix]     = fmaxf(acc[mt][nt][1] + b1, 0.f);
            op[pix + 8]           = fmaxf(acc[mt][nt][2] + b0, 0.f);
            op[HH * WW + pix + 8] = fmaxf(acc[mt][nt][3] + b1, 0.f);
        }
    }
}

// ---------------------------------------------------------------------------
extern "C" void kernel_launch(void* const* d_in, const int* in_sizes, int n_in,
                              void* d_out, int out_size) {
    const float* x      = (const float*)d_in[0];   // (8,64,128,128)
    const float* guide  = (const float*)d_in[1];   // (8,16,128,128)
    const float* weight = (const float*)d_in[2];   // (64,64,3,3)
    const float* bias   = (const float*)d_in[3];   // (64,)
    float* out = (float*)d_out;                    // (8,64,128,128)

    (void)in_sizes; (void)n_in; (void)out_size;

    cudaFuncSetAttribute(pac_mma, cudaFuncAttributeMaxDynamicSharedMemorySize,
                         SMEM_TOTAL);

    weight_split<<<(9 * 4 * 4 * 32 * 4 + 255) / 256, 256>>>(weight);

    dim3 grid(HH, BB);
    pac_mma<<<grid, 512, SMEM_TOTAL>>>(x, guide, bias, out);
}

// round 12
// speedup vs baseline: 2.9227x; 1.0301x over previous
#include <cuda_runtime.h>
#include <cuda_fp16.h>
#include <math.h>
#include <stdint.h>

#define BB   8
#define CIN  64
#define COUT 64
#define CG   16
#define HH   128
#define WW   128

// weight fragments fp16x2: [p(9)][kt(4)][ng(4)][lane(32)][j(4)]
// j = nt_local*2 + r ; o = (ng*2+nt_local)*8 + lane/4 ; c = kt*16 + (lane%4)*2 + r*8
__device__ uint32_t g_wfrag[9 * 4 * 4 * 32 * 4];

// smem layout (bytes)
#define SOFF_BIAS 0                       // 256
#define SOFF_KERN 256                     // 2 rows * 9 * 128 * 4B = 9216
#define SOFF_XH   9472                    // [dh(4)][col(130)][c(64 pad 72)] fp16
#define SMEM_TOTAL (9472 + 4 * 130 * 72 * 2)   // 84352

__device__ __forceinline__ uint32_t smem_u32(const void* p) {
    uint32_t a;
    asm("{ .reg .u64 t; cvta.to.shared.u64 t, %1; cvt.u32.u64 %0, t; }"
        : "=r"(a) : "l"(p));
    return a;
}
__device__ __forceinline__ void ldm_x4(uint32_t r[4], uint32_t addr) {
    asm volatile("ldmatrix.sync.aligned.m8n8.x4.shared.b16 {%0,%1,%2,%3}, [%4];"
                 : "=r"(r[0]), "=r"(r[1]), "=r"(r[2]), "=r"(r[3]) : "r"(addr));
}
__device__ __forceinline__ uint32_t hmul2(uint32_t a, uint32_t k) {
    uint32_t d;
    asm("mul.f16x2 %0, %1, %2;" : "=r"(d) : "r"(a), "r"(k));
    return d;
}
#define MMA_F16(d, a, b0, b1)                                                  \
    asm volatile("mma.sync.aligned.m16n8k16.row.col.f32.f16.f16.f32 "          \
                 "{%0,%1,%2,%3}, {%4,%5,%6,%7}, {%8,%9}, {%0,%1,%2,%3};"       \
                 : "+f"((d)[0]), "+f"((d)[1]), "+f"((d)[2]), "+f"((d)[3])      \
                 : "r"((a)[0]), "r"((a)[1]), "r"((a)[2]), "r"((a)[3]),         \
                   "r"(b0), "r"(b1))

// ---------------------------------------------------------------------------
// weight prep: mma B-fragment order, fp16 (unchanged — proven)
// ---------------------------------------------------------------------------
__global__ void weight_split(const float* __restrict__ weight) {
    int i = blockIdx.x * 256 + threadIdx.x;
    if (i >= 9 * 4 * 4 * 32 * 4) return;
    int p    = i >> 11;
    int kt   = (i >> 9) & 3;
    int ng   = (i >> 7) & 3;
    int lane = (i >> 2) & 31;
    int j    = i & 3;
    int o = (ng * 2 + (j >> 1)) * 8 + (lane >> 2);
    int c = kt * 16 + (lane & 3) * 2 + (j & 1) * 8;
    __half h0 = __float2half_rn(weight[((size_t)o * CIN + c) * 9 + p]);
    __half h1 = __float2half_rn(weight[((size_t)o * CIN + c + 1) * 9 + p]);
    g_wfrag[i] = ((uint32_t)__half_as_ushort(h1) << 16) | __half_as_ushort(h0);
}

// ---------------------------------------------------------------------------
// Main: one CTA = TWO output rows (256 M-positions). M8N2 warp tile, mt=2:
// each warp = 32 pixels (one row) x 32 couts -> 2.0 L1-wavefronts per MMA.
// kv folded into A (f16x2), B via LDG.128 from L2, barrier-free mainloop.
// 16 warps: warpM = wid&7 (row = warpM>>2, pixblock = (warpM&3)*32),
//           warpN = wid>>3 (32 couts).
// ---------------------------------------------------------------------------
__global__ __launch_bounds__(512, 1)
void pac_mma(const float* __restrict__ x,
             const float* __restrict__ guide,
             const float* __restrict__ bias,
             float* __restrict__ out) {
    extern __shared__ __align__(16) char smem[];
    const uint32_t sb = smem_u32(smem);
    float*    bias_s = (float*)(smem + SOFF_BIAS);
    uint32_t* kern_s = (uint32_t*)(smem + SOFF_KERN);   // [row][p][pix] half2(kv,kv)
    __half*   xh_s   = (__half*)(smem + SOFF_XH);

    const int tid   = threadIdx.x;
    const int lane  = tid & 31;
    const int wid   = tid >> 5;
    const int warpM = wid & 7;
    const int warpN = wid >> 3;
    const int h0 = blockIdx.x * 2;
    const int b  = blockIdx.y;

    if (tid < 256) {
        // ---- gaussian taps for both rows (parallel with staging) ----
        const int row = tid >> 7;
        const int pix = tid & 127;
        const int hr  = h0 + row;
        const float* gb = guide + (size_t)b * CG * HH * WW;
        float gc[CG];
#pragma unroll
        for (int c = 0; c < CG; c++)
            gc[c] = __ldg(&gb[c * HH * WW + hr * WW + pix]);
#pragma unroll
        for (int p = 0; p < 9; p++) {
            int gr = hr - 1 + p / 3;
            int gw = pix - 1 + p % 3;
            float ss = 0.f;
            if (gr >= 0 && gr < HH && gw >= 0 && gw < WW) {
#pragma unroll
                for (int c = 0; c < CG; c++) {
                    float d = __ldg(&gb[c * HH * WW + gr * WW + gw]) - gc[c];
                    ss = fmaf(d, d, ss);
                }
            } else {
#pragma unroll
                for (int c = 0; c < CG; c++) ss = fmaf(gc[c], gc[c], ss);
            }
            float kv = __expf(-0.5f * ss);
            uint32_t u = __half_as_ushort(__float2half_rn(kv));
            kern_s[(row * 9 + p) * 128 + pix] = (u << 16) | u;
        }
        if (tid < COUT) bias_s[tid] = bias[tid];
    } else {
        // ---- stage x halo fp16, [dh(4)][col(130)][c] stride 72; STS.128 ----
        const int t = tid - 256;
        for (int i = t; i < 4160; i += 256) {   // 4 dh * 8 c_oct * 130 col
            int col = i % 130;
            int q   = i / 130;
            int c0  = (q & 7) * 8;
            int dh  = q >> 3;
            int gr = h0 - 1 + dh, gc = col - 1;
            const bool ok = (gr >= 0) && (gr < HH) && (gc >= 0) && (gc < WW);
            const float* xp = x + ((size_t)(b * CIN + c0) * HH + gr) * WW + gc;
            __half hv[8];
#pragma unroll
            for (int j = 0; j < 8; j++) {
                float v = ok ? __ldg(xp + (size_t)j * (HH * WW)) : 0.f;
                hv[j] = __float2half_rn(v);
            }
            *(uint4*)(xh_s + (dh * 130 + col) * 72 + c0) = *(const uint4*)hv;
        }
    }
    __syncthreads();

    float acc[2][4][4];
#pragma unroll
    for (int i = 0; i < 2; i++)
#pragma unroll
        for (int j = 0; j < 4; j++)
#pragma unroll
            for (int k = 0; k < 4; k++) acc[i][j][k] = 0.f;

    const int row  = warpM >> 2;            // output row within CTA
    const int pixb = (warpM & 3) * 32;      // 32-pixel block within row
    const uint32_t a_base = sb + SOFF_XH + (uint32_t)(row * 18720) +
        (uint32_t)(((pixb + (lane & 15)) * 72 + ((lane >> 4) << 3)) * 2);
    const uint4* b_base = (const uint4*)g_wfrag + warpN * 64 + lane;
    const int pix0 = pixb + (lane >> 2);
    const int krow = row * 9 * 128;

    // ---- mainloop: 9 taps, barrier-free, kv folded into A ----
#pragma unroll
    for (int p = 0; p < 9; p++) {
        const int dh = p / 3, dw = p - dh * 3;
        const uint32_t a_tap = a_base + (uint32_t)((dh * 130 + dw) * 144);
        const uint4* bt = b_base + (size_t)(p * 4) * 128;

        uint32_t kv2[2][2];
        if (p != 4) {                 // center tap: kv == 1 exactly, skip fold
#pragma unroll
            for (int mt = 0; mt < 2; mt++) {
                kv2[mt][0] = kern_s[krow + p * 128 + pix0 + mt * 16];
                kv2[mt][1] = kern_s[krow + p * 128 + pix0 + mt * 16 + 8];
            }
        }

#pragma unroll
        for (int kt = 0; kt < 4; kt++) {
            uint4 b0 = __ldg(bt + (size_t)kt * 128);
            uint4 b1 = __ldg(bt + (size_t)kt * 128 + 32);
#pragma unroll
            for (int mt = 0; mt < 2; mt++) {
                uint32_t A[4];
                ldm_x4(A, a_tap + (uint32_t)(kt * 32 + mt * 2304));
                if (p != 4) {
                    // row map: A[0],A[2] -> pixel g ; A[1],A[3] -> pixel g+8
                    A[0] = hmul2(A[0], kv2[mt][0]);
                    A[2] = hmul2(A[2], kv2[mt][0]);
                    A[1] = hmul2(A[1], kv2[mt][1]);
                    A[3] = hmul2(A[3], kv2[mt][1]);
                }
                MMA_F16(acc[mt][0], A, b0.x, b0.y);
                MMA_F16(acc[mt][1], A, b0.z, b0.w);
                MMA_F16(acc[mt][2], A, b1.x, b1.y);
                MMA_F16(acc[mt][3], A, b1.z, b1.w);
            }
        }
    }

    // ---- epilogue: bias + relu ----
    const int hr = h0 + row;
#pragma unroll
    for (int mt = 0; mt < 2; mt++) {
        const int pix = pix0 + mt * 16;
#pragma unroll
        for (int nt = 0; nt < 4; nt++) {
            int o = (warpN * 4 + nt) * 8 + (lane & 3) * 2;
            float b0 = bias_s[o], b1 = bias_s[o + 1];
            float* op = out + (((size_t)b * COUT + o) * HH + hr) * WW;
            op[pix]               = fmaxf(acc[mt][nt][0] + b0, 0.f);
            op[HH * WW + pix]     = fmaxf(acc[mt][nt][1] + b1, 0.f);
            op[pix + 8]           = fmaxf(acc[mt][nt][2] + b0, 0.f);
            op[HH * WW + pix + 8] = fmaxf(acc[mt][nt][3] + b1, 0.f);
        }
    }
}

// ---------------------------------------------------------------------------
extern "C" void kernel_launch(void* const* d_in, const int* in_sizes, int n_in,
                              void* d_out, int out_size) {
    const float* x      = (const float*)d_in[0];   // (8,64,128,128)
    const float* guide  = (const float*)d_in[1];   // (8,16,128,128)
    const float* weight = (const float*)d_in[2];   // (64,64,3,3)
    const float* bias   = (const float*)d_in[3];   // (64,)
    float* out = (float*)d_out;                    // (8,64,128,128)

    (void)in_sizes; (void)n_in; (void)out_size;

    cudaFuncSetAttribute(pac_mma, cudaFuncAttributeMaxDynamicSharedMemorySize,
                         SMEM_TOTAL);

    weight_split<<<(9 * 4 * 4 * 32 * 4 + 255) / 256, 256>>>(weight);

    dim3 grid(HH / 2, BB);
    pac_mma<<<grid, 512, SMEM_TOTAL>>>(x, guide, bias, out);
}

// round 13
// speedup vs baseline: 3.1942x; 1.0929x over previous
#include <cuda_runtime.h>
#include <cuda_fp16.h>
#include <math.h>
#include <stdint.h>

#define BB   8
#define CIN  64
#define COUT 64
#define CG   16
#define HH   128
#define WW   128

// weight fragments fp16x2: [p(9)][kt(4)][ng(4)][lane(32)][j(4)]
// j = nt_local*2 + r ; o = (ng*2+nt_local)*8 + lane/4 ; c = kt*16 + (lane%4)*2 + r*8
__device__ uint32_t g_wfrag[9 * 4 * 4 * 32 * 4];

// smem layout (bytes)
#define SOFF_BIAS 0                    // 256
#define SOFF_KERN 256                  // 9*128*4 = 4608
#define SOFF_XH   4864                 // [dh(3)][col(130)][c(64 pad 72)] fp16
#define SMEM_TOTAL (4864 + 3 * 130 * 72 * 2)   // 61024

__device__ __forceinline__ uint32_t smem_u32(const void* p) {
    uint32_t a;
    asm("{ .reg .u64 t; cvta.to.shared.u64 t, %1; cvt.u32.u64 %0, t; }"
        : "=r"(a) : "l"(p));
    return a;
}
__device__ __forceinline__ void ldm_x4(uint32_t r[4], uint32_t addr) {
    asm volatile("ldmatrix.sync.aligned.m8n8.x4.shared.b16 {%0,%1,%2,%3}, [%4];"
                 : "=r"(r[0]), "=r"(r[1]), "=r"(r[2]), "=r"(r[3]) : "r"(addr));
}
__device__ __forceinline__ uint32_t hmul2(uint32_t a, uint32_t k) {
    uint32_t d;
    asm("mul.f16x2 %0, %1, %2;" : "=r"(d) : "r"(a), "r"(k));
    return d;
}
#define MMA_F16(d, a, b0, b1)                                                  \
    asm volatile("mma.sync.aligned.m16n8k16.row.col.f32.f16.f16.f32 "          \
                 "{%0,%1,%2,%3}, {%4,%5,%6,%7}, {%8,%9}, {%0,%1,%2,%3};"       \
                 : "+f"((d)[0]), "+f"((d)[1]), "+f"((d)[2]), "+f"((d)[3])      \
                 : "r"((a)[0]), "r"((a)[1]), "r"((a)[2]), "r"((a)[3]),         \
                   "r"(b0), "r"(b1))

// ---------------------------------------------------------------------------
// weight prep: mma B-fragment order, fp16 (unchanged — proven)
// ---------------------------------------------------------------------------
__global__ void weight_split(const float* __restrict__ weight) {
    int i = blockIdx.x * 256 + threadIdx.x;
    if (i >= 9 * 4 * 4 * 32 * 4) return;
    int p    = i >> 11;
    int kt   = (i >> 9) & 3;
    int ng   = (i >> 7) & 3;
    int lane = (i >> 2) & 31;
    int j    = i & 3;
    int o = (ng * 2 + (j >> 1)) * 8 + (lane >> 2);
    int c = kt * 16 + (lane & 3) * 2 + (j & 1) * 8;
    __half h0 = __float2half_rn(weight[((size_t)o * CIN + c) * 9 + p]);
    __half h1 = __float2half_rn(weight[((size_t)o * CIN + c + 1) * 9 + p]);
    g_wfrag[i] = ((uint32_t)__half_as_ushort(h1) << 16) | __half_as_ushort(h0);
}

// ---------------------------------------------------------------------------
// Main: one CTA = ONE output row, 256 threads, 3 CTAs/SM.
// 8 warps: warpM = wid&3 (32-pixel block), warpN = wid>>2 (32 couts).
// Warp tile 32pix x 32cout (2.0 L1-wavefronts/MMA), kv folded into A,
// B via LDG.128 from L2, barrier-free mainloop.
// ---------------------------------------------------------------------------
__global__ __launch_bounds__(256, 3)
void pac_mma(const float* __restrict__ x,
             const float* __restrict__ guide,
             const float* __restrict__ bias,
             float* __restrict__ out) {
    extern __shared__ __align__(16) char smem[];
    const uint32_t sb = smem_u32(smem);
    float*    bias_s = (float*)(smem + SOFF_BIAS);
    uint32_t* kern_s = (uint32_t*)(smem + SOFF_KERN);   // [p][pix] half2(kv,kv)
    __half*   xh_s   = (__half*)(smem + SOFF_XH);

    const int tid   = threadIdx.x;
    const int lane  = tid & 31;
    const int wid   = tid >> 5;
    const int warpM = wid & 3;
    const int warpN = wid >> 2;
    const int h = blockIdx.x;
    const int b = blockIdx.y;

    // ---- stage x halo fp16, [dh(3)][col(130)][c] stride 72; STS.128 ----
    for (int i = tid; i < 3120; i += 256) {   // 3 dh * 8 c_oct * 130 col
        int col = i % 130;
        int q   = i / 130;
        int c0  = (q & 7) * 8;
        int dh  = q >> 3;
        int gr = h - 1 + dh, gc = col - 1;
        const bool ok = (gr >= 0) && (gr < HH) && (gc >= 0) && (gc < WW);
        const float* xp = x + ((size_t)(b * CIN + c0) * HH + gr) * WW + gc;
        __half hv[8];
#pragma unroll
        for (int j = 0; j < 8; j++) {
            float v = ok ? __ldg(xp + (size_t)j * (HH * WW)) : 0.f;
            hv[j] = __float2half_rn(v);
        }
        *(uint4*)(xh_s + (dh * 130 + col) * 72 + c0) = *(const uint4*)hv;
    }
    if (tid < COUT) bias_s[tid] = bias[tid];

    // ---- gaussian taps from global guide (L2-hot), store half2(kv,kv) ----
    if (tid < 128) {
        const int pix = tid;
        const float* gb = guide + (size_t)b * CG * HH * WW;
        float gc[CG];
#pragma unroll
        for (int c = 0; c < CG; c++)
            gc[c] = __ldg(&gb[c * HH * WW + h * WW + pix]);
#pragma unroll
        for (int p = 0; p < 9; p++) {
            int gr = h - 1 + p / 3;
            int gw = pix - 1 + p % 3;
            float ss = 0.f;
            if (gr >= 0 && gr < HH && gw >= 0 && gw < WW) {
#pragma unroll
                for (int c = 0; c < CG; c++) {
                    float d = __ldg(&gb[c * HH * WW + gr * WW + gw]) - gc[c];
                    ss = fmaf(d, d, ss);
                }
            } else {
#pragma unroll
                for (int c = 0; c < CG; c++) ss = fmaf(gc[c], gc[c], ss);
            }
            float kv = __expf(-0.5f * ss);
            uint32_t u = __half_as_ushort(__float2half_rn(kv));
            kern_s[p * 128 + pix] = (u << 16) | u;
        }
    }
    __syncthreads();

    float acc[2][4][4];
#pragma unroll
    for (int i = 0; i < 2; i++)
#pragma unroll
        for (int j = 0; j < 4; j++)
#pragma unroll
            for (int k = 0; k < 4; k++) acc[i][j][k] = 0.f;

    const int pixb = warpM * 32;
    const uint32_t a_base = sb + SOFF_XH +
        (uint32_t)(((pixb + (lane & 15)) * 72 + ((lane >> 4) << 3)) * 2);
    const uint4* b_base = (const uint4*)g_wfrag + warpN * 64 + lane;
    const int pix0 = pixb + (lane >> 2);

    // ---- mainloop: 9 taps, barrier-free, kv folded into A ----
#pragma unroll
    for (int p = 0; p < 9; p++) {
        const int dh = p / 3, dw = p - dh * 3;
        const uint32_t a_tap = a_base + (uint32_t)((dh * 130 + dw) * 144);
        const uint4* bt = b_base + (size_t)(p * 4) * 128;

        uint32_t kv2[2][2];
        if (p != 4) {                 // center tap: kv == 1 exactly, skip fold
#pragma unroll
            for (int mt = 0; mt < 2; mt++) {
                kv2[mt][0] = kern_s[p * 128 + pix0 + mt * 16];
                kv2[mt][1] = kern_s[p * 128 + pix0 + mt * 16 + 8];
            }
        }

#pragma unroll
        for (int kt = 0; kt < 4; kt++) {
            uint4 b0 = __ldg(bt + (size_t)kt * 128);
            uint4 b1 = __ldg(bt + (size_t)kt * 128 + 32);
#pragma unroll
            for (int mt = 0; mt < 2; mt++) {
                uint32_t A[4];
                ldm_x4(A, a_tap + (uint32_t)(kt * 32 + mt * 2304));
                if (p != 4) {
                    // row map: A[0],A[2] -> pixel g ; A[1],A[3] -> pixel g+8
                    A[0] = hmul2(A[0], kv2[mt][0]);
                    A[2] = hmul2(A[2], kv2[mt][0]);
                    A[1] = hmul2(A[1], kv2[mt][1]);
                    A[3] = hmul2(A[3], kv2[mt][1]);
                }
                MMA_F16(acc[mt][0], A, b0.x, b0.y);
                MMA_F16(acc[mt][1], A, b0.z, b0.w);
                MMA_F16(acc[mt][2], A, b1.x, b1.y);
                MMA_F16(acc[mt][3], A, b1.z, b1.w);
            }
        }
    }

    // ---- epilogue: bias + relu ----
#pragma unroll
    for (int mt = 0; mt < 2; mt++) {
        const int pix = pix0 + mt * 16;
#pragma unroll
        for (int nt = 0; nt < 4; nt++) {
            int o = (warpN * 4 + nt) * 8 + (lane & 3) * 2;
            float b0 = bias_s[o], b1 = bias_s[o + 1];
            float* op = out + (((size_t)b * COUT + o) * HH + h) * WW;
            op[pix]               = fmaxf(acc[mt][nt][0] + b0, 0.f);
            op[HH * WW + pix]     = fmaxf(acc[mt][nt][1] + b1, 0.f);
            op[pix + 8]           = fmaxf(acc[mt][nt][2] + b0, 0.f);
            op[HH * WW + pix + 8] = fmaxf(acc[mt][nt][3] + b1, 0.f);
        }
    }
}

// ---------------------------------------------------------------------------
extern "C" void kernel_launch(void* const* d_in, const int* in_sizes, int n_in,
                              void* d_out, int out_size) {
    const float* x      = (const float*)d_in[0];   // (8,64,128,128)
    const float* guide  = (const float*)d_in[1];   // (8,16,128,128)
    const float* weight = (const float*)d_in[2];   // (64,64,3,3)
    const float* bias   = (const float*)d_in[3];   // (64,)
    float* out = (float*)d_out;                    // (8,64,128,128)

    (void)in_sizes; (void)n_in; (void)out_size;

    cudaFuncSetAttribute(pac_mma, cudaFuncAttributeMaxDynamicSharedMemorySize,
                         SMEM_TOTAL);

    weight_split<<<(9 * 4 * 4 * 32 * 4 + 255) / 256, 256>>>(weight);

    dim3 grid(HH, BB);
    pac_mma<<<grid, 256, SMEM_TOTAL>>>(x, guide, bias, out);
}